// round 11
// baseline (speedup 1.0000x reference)
#include <cuda_runtime.h>
#include <cuda_fp16.h>
#include <cstdint>

// Problem constants
#define N_FEAT  65536
#define N_PROTO 512
#define DIMK    256

#define BLK_M   256                 // feature rows per CTA
#define GRP_N   32                  // protos per group-chunk
#define N_CHUNKS 4                  // chunks per group (4 * 32 = 128 protos/group)

// SMEM layout (bytes)
#define SM_FSQ   0                          // 256 floats = 1024 B
#define SM_PSQ   1024                       // 512 floats = 2048 B
#define SM_A     4096                       // 16 mtiles * 16 ksteps * 512 B = 131072
#define SM_B     (SM_A + 131072)            // 4 groups * (4 ntiles*16 s*256 B = 16384)
#define GRP_B_BYTES 16384
#define SMEM_TOTAL (SM_B + 4 * GRP_B_BYTES) // 200704 B

// pack float2 -> fp16x2 (x -> low half)
__device__ __forceinline__ uint32_t pk(float2 f) {
    __half2 h = __floats2half2_rn(f.x, f.y);
    return *(uint32_t*)&h;
}

// m16n8k16 fp16 MMA, fp16 accumulate (2-reg accumulator)
__device__ __forceinline__ void mma_f16acc(uint32_t d[2], const uint32_t a[4], const uint32_t b[2]) {
    asm volatile(
        "mma.sync.aligned.m16n8k16.row.col.f16.f16.f16.f16 "
        "{%0,%1}, {%2,%3,%4,%5}, {%6,%7}, {%0,%1};"
        : "+r"(d[0]), "+r"(d[1])
        : "r"(a[0]), "r"(a[1]), "r"(a[2]), "r"(a[3]),
          "r"(b[0]), "r"(b[1]));
}

// named barrier over 128 threads (one nj-group = 4 warps)
__device__ __forceinline__ void grp_bar(int id) {
    asm volatile("bar.sync %0, 128;" :: "r"(id) : "memory");
}

// ---------------------------------------------------------------------------
// Four independent 4-warp groups per CTA (grp = nj = wid & 3). Each group owns
// a 128-proto quarter, a private B staging region, and a private named barrier.
// Fragment SMEM layout (identity lane map, conflict-free):
//   A slab (mtile t, kstep s): 32 lanes x uint4 = 512 B
//   B slab (ntile u, kstep s): 32 lanes x uint2 = 256 B
// Per-warp register tile: T=4 mtiles x U=4 ntiles -> 6 SMEM bytes per MMA.
// fp16 accumulators (32 regs) leave ~50 regs of scheduling slack for ptxas.
// ---------------------------------------------------------------------------
__global__ void __launch_bounds__(512, 1) proto_dist_kernel(
    const float* __restrict__ feat,
    const float* __restrict__ proto,
    float* __restrict__ out1,    // [N, P]
    float* __restrict__ out2)    // [P, N]
{
    extern __shared__ char smem[];
    float* s_fsq = (float*)(smem + SM_FSQ);
    float* s_psq = (float*)(smem + SM_PSQ);

    const int tid  = threadIdx.x;
    const int lane = tid & 31;
    const int wid  = tid >> 5;     // 0..15
    const int g    = lane >> 2;
    const int tig  = lane & 3;
    const int m0   = blockIdx.x * BLK_M;

    const int mi   = wid >> 2;     // 0..3 — M position (T=4 -> 64 rows per warp)
    const int nj   = wid & 3;      // 0..3 — group / N position

    // ---- Stage A tile (256 x 256) as fp16 fragments + exact fp32 feat norms ----
    {
        const int t = wid;                       // warp w stages mtile w
        const float* rA = feat + (size_t)(m0 + t * 16 + g) * DIMK;
        const float* rB = rA + 8 * DIMK;
        float sqA = 0.f, sqB = 0.f;
#pragma unroll
        for (int s = 0; s < 16; s++) {
            const int kA = s * 16 + 2 * tig;
            float2 f0 = *(const float2*)(rA + kA);
            float2 f1 = *(const float2*)(rB + kA);
            float2 f2 = *(const float2*)(rA + kA + 8);
            float2 f3 = *(const float2*)(rB + kA + 8);
            sqA += f0.x * f0.x + f0.y * f0.y + f2.x * f2.x + f2.y * f2.y;
            sqB += f1.x * f1.x + f1.y * f1.y + f3.x * f3.x + f3.y * f3.y;
            uint4 w;
            w.x = pk(f0); w.y = pk(f1); w.z = pk(f2); w.w = pk(f3);
            *(uint4*)(smem + SM_A + (size_t)((t * 16 + s) * 32 + lane) * 16) = w;
        }
        sqA += __shfl_xor_sync(0xffffffffu, sqA, 1);
        sqA += __shfl_xor_sync(0xffffffffu, sqA, 2);
        sqB += __shfl_xor_sync(0xffffffffu, sqB, 1);
        sqB += __shfl_xor_sync(0xffffffffu, sqB, 2);
        if (tig == 0) {
            s_fsq[t * 16 + g]     = sqA;
            s_fsq[t * 16 + g + 8] = sqB;
        }
    }

    // ---- All 512 prototype norms, exact fp32 (proto is L2-hot: 512 KB) ----
    {
        const float4* r = (const float4*)(proto + (size_t)tid * DIMK);
        float s0 = 0.f, s1 = 0.f, s2 = 0.f, s3 = 0.f;
#pragma unroll
        for (int j = 0; j < 64; j += 4) {
            float4 v0 = r[j], v1 = r[j + 1], v2 = r[j + 2], v3 = r[j + 3];
            s0 += v0.x * v0.x + v0.y * v0.y + v0.z * v0.z + v0.w * v0.w;
            s1 += v1.x * v1.x + v1.y * v1.y + v1.z * v1.z + v1.w * v1.w;
            s2 += v2.x * v2.x + v2.y * v2.y + v2.z * v2.z + v2.w * v2.w;
            s3 += v3.x * v3.x + v3.y * v3.y + v3.z * v3.z + v3.w * v3.w;
        }
        s_psq[tid] = (s0 + s1) + (s2 + s3);
    }

    // ---- B staging: warp (mi, nj) stages ntile u=mi of group nj's chunk c ----
    char* const grpB = smem + SM_B + nj * GRP_B_BYTES;
    const int pgrp = nj * 128;           // group's proto quarter
    auto stage_B = [&](int c) {
        const float* r = proto + (size_t)(pgrp + c * GRP_N + mi * 8 + g) * DIMK;
#pragma unroll
        for (int s = 0; s < 16; s++) {
            const int kA = s * 16 + 2 * tig;
            float2 f0 = *(const float2*)(r + kA);
            float2 f1 = *(const float2*)(r + kA + 8);
            uint2 w;
            w.x = pk(f0); w.y = pk(f1);
            *(uint2*)(grpB + (size_t)((mi * 16 + s) * 32 + lane) * 8) = w;
        }
    };

    stage_B(0);
    __syncthreads();   // A frags + norms + all groups' B(chunk 0) visible

    const char* baseA = smem + SM_A + (size_t)lane * 16;
    const char* baseB = grpB + (size_t)lane * 8;
    const int bar_id = 1 + nj;

    for (int c = 0; c < N_CHUNKS; c++) {
        const int p0 = pgrp + c * GRP_N;

        uint32_t acc[4][4][2];
#pragma unroll
        for (int tp = 0; tp < 4; tp++)
#pragma unroll
            for (int up = 0; up < 4; up++) {
                acc[tp][up][0] = 0u;
                acc[tp][up][1] = 0u;
            }

#pragma unroll
        for (int s = 0; s < 16; s++) {
            uint4 a[4];
#pragma unroll
            for (int tp = 0; tp < 4; tp++)
                a[tp] = *(const uint4*)(baseA + (size_t)(((mi * 4 + tp) * 16 + s)) * 512);
            uint2 b[4];
#pragma unroll
            for (int up = 0; up < 4; up++)
                b[up] = *(const uint2*)(baseB + (size_t)((up * 16 + s) * 32) * 8);
#pragma unroll
            for (int tp = 0; tp < 4; tp++)
#pragma unroll
                for (int up = 0; up < 4; up++)
                    mma_f16acc(acc[tp][up], (const uint32_t*)&a[tp], (const uint32_t*)&b[up]);
        }

        grp_bar(bar_id);   // group done reading B(chunk c); buffer free

        // Stage next chunk's B: LDG latency drains under the epilogue stores.
        if (c + 1 < N_CHUNKS) stage_B(c + 1);

        // ---- Fused distance epilogue: direct stores for BOTH outputs ----
#pragma unroll
        for (int tp = 0; tp < 4; tp++) {
            const int ml0 = mi * 64 + tp * 16 + g;
            const int ml1 = ml0 + 8;
            const float fs0 = s_fsq[ml0];
            const float fs1 = s_fsq[ml1];
            float* o1a = out1 + (size_t)(m0 + ml0) * N_PROTO + p0;
            float* o1b = out1 + (size_t)(m0 + ml1) * N_PROTO + p0;
#pragma unroll
            for (int up = 0; up < 4; up++) {
                const int pl = up * 8 + 2 * tig;
                const float2 ps = *(const float2*)(s_psq + p0 + pl);
                const float2 lo = __half22float2(*(const __half2*)&acc[tp][up][0]); // c0,c1
                const float2 hi = __half22float2(*(const __half2*)&acc[tp][up][1]); // c2,c3
                const float d0 = fs0 + ps.x - 2.0f * lo.x;
                const float d1 = fs0 + ps.y - 2.0f * lo.y;
                const float d2 = fs1 + ps.x - 2.0f * hi.x;
                const float d3 = fs1 + ps.y - 2.0f * hi.y;
                // out1 [N,P]: 4 tig-lanes x float2 = full 32B sector per row
                *(float2*)(o1a + pl) = make_float2(d0, d1);
                *(float2*)(o1b + pl) = make_float2(d2, d3);
                // out2 [P,N]: 8 g-lanes x 4B = full 32B sector per column
                float* o2 = out2 + (size_t)(p0 + pl) * N_FEAT + m0;
                o2[ml0]          = d0;
                o2[N_FEAT + ml0] = d1;
                o2[ml1]          = d2;
                o2[N_FEAT + ml1] = d3;
            }
        }

        // B(chunk c+1) visible to this group's 4 warps.
        if (c + 1 < N_CHUNKS) grp_bar(bar_id);
    }
}

// ---------------------------------------------------------------------------
// Launch
// ---------------------------------------------------------------------------
extern "C" void kernel_launch(void* const* d_in, const int* in_sizes, int n_in,
                              void* d_out, int out_size)
{
    (void)in_sizes; (void)n_in; (void)out_size;
    const float* feat  = (const float*)d_in[0];
    const float* proto = (const float*)d_in[1];
    float* out1 = (float*)d_out;
    float* out2 = out1 + (size_t)N_FEAT * N_PROTO;

    cudaFuncSetAttribute(proto_dist_kernel,
                         cudaFuncAttributeMaxDynamicSharedMemorySize, SMEM_TOTAL);

    proto_dist_kernel<<<N_FEAT / BLK_M, 512, SMEM_TOTAL>>>(feat, proto, out1, out2);
}

// round 12
// speedup vs baseline: 1.0207x; 1.0207x over previous
#include <cuda_runtime.h>
#include <cuda_fp16.h>
#include <cstdint>

// Problem constants
#define N_FEAT  65536
#define N_PROTO 512
#define DIMK    256

#define BLK_M   256                 // feature rows per CTA
#define BLK_N   128                 // prototypes per chunk
#define N_CHUNKS (N_PROTO / BLK_N)  // 4

// SMEM layout (bytes)
#define SM_FSQ   0                          // 256 floats = 1024 B
#define SM_PSQ   1024                       // 512 floats = 2048 B
#define SM_A     4096                       // 16 mtiles * 16 ksteps * 512 B = 131072
#define SM_B     (SM_A + 131072)            // 16 ntiles * 16 ksteps * 256 B = 65536
#define SMEM_TOTAL (SM_B + 65536)           // 200704 B

// pack float2 -> fp16x2 (x -> low half)
__device__ __forceinline__ uint32_t pk(float2 f) {
    __half2 h = __floats2half2_rn(f.x, f.y);
    return *(uint32_t*)&h;
}

// m16n8k16 fp16 MMA, fp32 accumulate
__device__ __forceinline__ void mma_f16(float d[4], const uint32_t a[4], const uint32_t b[2]) {
    asm volatile(
        "mma.sync.aligned.m16n8k16.row.col.f32.f16.f16.f32 "
        "{%0,%1,%2,%3}, {%4,%5,%6,%7}, {%8,%9}, {%0,%1,%2,%3};"
        : "+f"(d[0]), "+f"(d[1]), "+f"(d[2]), "+f"(d[3])
        : "r"(a[0]), "r"(a[1]), "r"(a[2]), "r"(a[3]),
          "r"(b[0]), "r"(b[1]));
}

// ---------------------------------------------------------------------------
// 256 threads (8 warps), 255 registers/thread: the register-heavy GEMM regime.
// Warp grid 2(M) x ... no: 4(M) x 2(N); per-warp tile 64x64 = T=4 mtiles x
// U=8 ntiles -> 128 fp32 accumulators + 32 fragment regs, ~40 regs of
// scheduling slack so ptxas can pipeline k-step loads under 32 MMAs.
// Fragment SMEM layout (identity lane map, conflict-free), same as R7:
//   A slab (mtile t, kstep s): 32 lanes x uint4 = 512 B
//   B slab (ntile u, kstep s): 32 lanes x uint2 = 256 B
// ---------------------------------------------------------------------------
__global__ void __launch_bounds__(256, 1) proto_dist_kernel(
    const float* __restrict__ feat,
    const float* __restrict__ proto,
    float* __restrict__ out1,    // [N, P]
    float* __restrict__ out2)    // [P, N]
{
    extern __shared__ char smem[];
    float* s_fsq = (float*)(smem + SM_FSQ);
    float* s_psq = (float*)(smem + SM_PSQ);

    const int tid  = threadIdx.x;
    const int lane = tid & 31;
    const int wid  = tid >> 5;     // 0..7
    const int g    = lane >> 2;
    const int tig  = lane & 3;
    const int m0   = blockIdx.x * BLK_M;

    const int mi   = wid >> 1;     // 0..3 — M position (64 rows per warp)
    const int nj   = wid & 1;      // 0..1 — N position (64 protos per warp)

    // ---- Stage A tile (256 x 256) as fp16 fragments + exact fp32 feat norms ----
    // 8 warps stage 16 mtiles: warp w stages mtiles 2w, 2w+1.
#pragma unroll
    for (int tt = 0; tt < 2; tt++) {
        const int t = wid * 2 + tt;
        const float* rA = feat + (size_t)(m0 + t * 16 + g) * DIMK;
        const float* rB = rA + 8 * DIMK;
        float sqA = 0.f, sqB = 0.f;
#pragma unroll
        for (int s = 0; s < 16; s++) {
            const int kA = s * 16 + 2 * tig;
            float2 f0 = *(const float2*)(rA + kA);
            float2 f1 = *(const float2*)(rB + kA);
            float2 f2 = *(const float2*)(rA + kA + 8);
            float2 f3 = *(const float2*)(rB + kA + 8);
            sqA += f0.x * f0.x + f0.y * f0.y + f2.x * f2.x + f2.y * f2.y;
            sqB += f1.x * f1.x + f1.y * f1.y + f3.x * f3.x + f3.y * f3.y;
            uint4 w;
            w.x = pk(f0); w.y = pk(f1); w.z = pk(f2); w.w = pk(f3);
            *(uint4*)(smem + SM_A + (size_t)((t * 16 + s) * 32 + lane) * 16) = w;
        }
        sqA += __shfl_xor_sync(0xffffffffu, sqA, 1);
        sqA += __shfl_xor_sync(0xffffffffu, sqA, 2);
        sqB += __shfl_xor_sync(0xffffffffu, sqB, 1);
        sqB += __shfl_xor_sync(0xffffffffu, sqB, 2);
        if (tig == 0) {
            s_fsq[t * 16 + g]     = sqA;
            s_fsq[t * 16 + g + 8] = sqB;
        }
    }

    // ---- All 512 prototype norms, exact fp32 (proto is L2-hot: 512 KB) ----
#pragma unroll
    for (int rr = 0; rr < 2; rr++) {
        const int row = rr * 256 + tid;
        const float4* r = (const float4*)(proto + (size_t)row * DIMK);
        float s0 = 0.f, s1 = 0.f;
#pragma unroll
        for (int j = 0; j < 64; j += 2) {
            float4 v0 = r[j], v1 = r[j + 1];
            s0 += v0.x * v0.x + v0.y * v0.y + v0.z * v0.z + v0.w * v0.w;
            s1 += v1.x * v1.x + v1.y * v1.y + v1.z * v1.z + v1.w * v1.w;
        }
        s_psq[row] = s0 + s1;
    }

    // ---- B staging: chunk c = 128 protos = 16 ntiles; warp w stages 2w, 2w+1 ----
    auto stage_B = [&](int c) {
#pragma unroll
        for (int tt = 0; tt < 2; tt++) {
            const int u = wid * 2 + tt;
            const float* r = proto + (size_t)(c * BLK_N + u * 8 + g) * DIMK;
#pragma unroll
            for (int s = 0; s < 16; s++) {
                const int kA = s * 16 + 2 * tig;
                float2 f0 = *(const float2*)(r + kA);
                float2 f1 = *(const float2*)(r + kA + 8);
                uint2 w;
                w.x = pk(f0); w.y = pk(f1);
                *(uint2*)(smem + SM_B + (size_t)((u * 16 + s) * 32 + lane) * 8) = w;
            }
        }
    };

    stage_B(0);
    __syncthreads();   // A frags + norms + B(chunk 0) visible

    const char* baseA = smem + SM_A + (size_t)lane * 16;
    const char* baseB = smem + SM_B + (size_t)lane * 8;

    for (int c = 0; c < N_CHUNKS; c++) {
        const int p0 = c * BLK_N;

        float acc[4][8][4];
#pragma unroll
        for (int tp = 0; tp < 4; tp++)
#pragma unroll
            for (int up = 0; up < 8; up++)
#pragma unroll
                for (int e = 0; e < 4; e++) acc[tp][up][e] = 0.f;

#pragma unroll
        for (int s = 0; s < 16; s++) {
            uint4 a[4];
#pragma unroll
            for (int tp = 0; tp < 4; tp++)
                a[tp] = *(const uint4*)(baseA + (size_t)((mi * 4 + tp) * 16 + s) * 512);
            uint2 b[8];
#pragma unroll
            for (int up = 0; up < 8; up++)
                b[up] = *(const uint2*)(baseB + (size_t)((nj * 8 + up) * 16 + s) * 256);
#pragma unroll
            for (int tp = 0; tp < 4; tp++)
#pragma unroll
                for (int up = 0; up < 8; up++)
                    mma_f16(acc[tp][up], (const uint32_t*)&a[tp], (const uint32_t*)&b[up]);
        }

        __syncthreads();   // B(chunk c) fully consumed; buffer free to rewrite

        // Next chunk's staging LDGs first: latency drains under the stores.
        if (c + 1 < N_CHUNKS) stage_B(c + 1);

        // ---- Fused distance epilogue: direct stores for BOTH outputs ----
#pragma unroll
        for (int tp = 0; tp < 4; tp++) {
            const int ml0 = mi * 64 + tp * 16 + g;
            const int ml1 = ml0 + 8;
            const float fs0 = s_fsq[ml0];
            const float fs1 = s_fsq[ml1];
            float* o1a = out1 + (size_t)(m0 + ml0) * N_PROTO + p0;
            float* o1b = out1 + (size_t)(m0 + ml1) * N_PROTO + p0;
#pragma unroll
            for (int up = 0; up < 8; up++) {
                const int pl = nj * 64 + up * 8 + 2 * tig;
                const float2 ps = *(const float2*)(s_psq + p0 + pl);
                const float d0 = fs0 + ps.x - 2.0f * acc[tp][up][0];
                const float d1 = fs0 + ps.y - 2.0f * acc[tp][up][1];
                const float d2 = fs1 + ps.x - 2.0f * acc[tp][up][2];
                const float d3 = fs1 + ps.y - 2.0f * acc[tp][up][3];
                // out1 [N,P]: 4 tig-lanes x float2 = full 32B sector per row
                *(float2*)(o1a + pl) = make_float2(d0, d1);
                *(float2*)(o1b + pl) = make_float2(d2, d3);
                // out2 [P,N]: 8 g-lanes x 4B = full 32B sector per column
                float* o2 = out2 + (size_t)(p0 + pl) * N_FEAT + m0;
                o2[ml0]          = d0;
                o2[N_FEAT + ml0] = d1;
                o2[ml1]          = d2;
                o2[N_FEAT + ml1] = d3;
            }
        }

        if (c + 1 < N_CHUNKS) __syncthreads();   // B(chunk c+1) visible
    }
}

// ---------------------------------------------------------------------------
// Launch
// ---------------------------------------------------------------------------
extern "C" void kernel_launch(void* const* d_in, const int* in_sizes, int n_in,
                              void* d_out, int out_size)
{
    (void)in_sizes; (void)n_in; (void)out_size;
    const float* feat  = (const float*)d_in[0];
    const float* proto = (const float*)d_in[1];
    float* out1 = (float*)d_out;
    float* out2 = out1 + (size_t)N_FEAT * N_PROTO;

    cudaFuncSetAttribute(proto_dist_kernel,
                         cudaFuncAttributeMaxDynamicSharedMemorySize, SMEM_TOTAL);

    proto_dist_kernel<<<N_FEAT / BLK_M, 256, SMEM_TOTAL>>>(feat, proto, out1, out2);
}

// round 13
// speedup vs baseline: 1.0658x; 1.0441x over previous
#include <cuda_runtime.h>
#include <cuda_fp16.h>
#include <cstdint>

// Problem constants
#define N_FEAT  65536
#define N_PROTO 512
#define DIMK    256

#define BLK_M   256                 // feature rows per CTA
#define BLK_N   32                  // protos per chunk
#define N_CHUNKS 16

// SMEM layout (bytes)
#define SM_FSQ   0                          // 256 floats
#define SM_PSQ   1024                       // 512 floats
#define SM_A     4096                       // 16 mtiles * 16 ksteps * 512 B = 131072
#define SM_B0    (SM_A + 131072)            // chunk buffer 0: 4 ntiles*16 s*256 B = 16384
#define SM_B1    (SM_B0 + 16384)            // chunk buffer 1
#define SMEM_TOTAL (SM_B1 + 16384)          // 167936 B

// pack float2 -> fp16x2 (x -> low half)
__device__ __forceinline__ uint32_t pk(float2 f) {
    __half2 h = __floats2half2_rn(f.x, f.y);
    return *(uint32_t*)&h;
}

// m16n8k16 fp16 MMA, fp32 accumulate
__device__ __forceinline__ void mma_f16(float d[4], const uint32_t a[4], const uint32_t b[2]) {
    asm volatile(
        "mma.sync.aligned.m16n8k16.row.col.f32.f16.f16.f32 "
        "{%0,%1,%2,%3}, {%4,%5,%6,%7}, {%8,%9}, {%0,%1,%2,%3};"
        : "+f"(d[0]), "+f"(d[1]), "+f"(d[2]), "+f"(d[3])
        : "r"(a[0]), "r"(a[1]), "r"(a[2]), "r"(a[3]),
          "r"(b[0]), "r"(b[1]));
}

// ---------------------------------------------------------------------------
// Software-pipelined epilogue: while chunk c's 16 k-steps run (4 LDS + 4 MMA
// each), chunk c-1's 24 stores are emitted 2 per k-step (s<12). Two 16-float
// accumulator sets alternate by chunk parity; distances are computed in-place
// at chunk entry. Fragment SMEM layout identical to R7 (identity lane map):
//   A slab (mtile t, kstep s): 32 lanes x uint4 = 512 B
//   B slab (ntile u, kstep s): 32 lanes x uint2 = 256 B
// Warp grid 8(M) x 2(N); per-warp tile T=2 mtiles x U=2 ntiles (32x16).
// ---------------------------------------------------------------------------
__global__ void __launch_bounds__(512, 1) proto_dist_kernel(
    const float* __restrict__ feat,
    const float* __restrict__ proto,
    float* __restrict__ out1,    // [N, P]
    float* __restrict__ out2)    // [P, N]
{
    extern __shared__ char smem[];
    float* s_fsq = (float*)(smem + SM_FSQ);
    float* s_psq = (float*)(smem + SM_PSQ);

    const int tid  = threadIdx.x;
    const int lane = tid & 31;
    const int wid  = tid >> 5;     // 0..15
    const int g    = lane >> 2;
    const int tig  = lane & 3;
    const int m0   = blockIdx.x * BLK_M;

    const int mi   = wid >> 1;     // 0..7 — M position
    const int nj   = wid & 1;      // 0..1 — N position

    // ---- Stage A tile (256 x 256) as fp16 fragments + exact fp32 feat norms ----
    {
        const int t = wid;                       // warp w stages mtile w
        const float* rA = feat + (size_t)(m0 + t * 16 + g) * DIMK;
        const float* rB = rA + 8 * DIMK;
        float sqA = 0.f, sqB = 0.f;
#pragma unroll
        for (int s = 0; s < 16; s++) {
            const int kA = s * 16 + 2 * tig;
            float2 f0 = *(const float2*)(rA + kA);
            float2 f1 = *(const float2*)(rB + kA);
            float2 f2 = *(const float2*)(rA + kA + 8);
            float2 f3 = *(const float2*)(rB + kA + 8);
            sqA += f0.x * f0.x + f0.y * f0.y + f2.x * f2.x + f2.y * f2.y;
            sqB += f1.x * f1.x + f1.y * f1.y + f3.x * f3.x + f3.y * f3.y;
            uint4 w;
            w.x = pk(f0); w.y = pk(f1); w.z = pk(f2); w.w = pk(f3);
            *(uint4*)(smem + SM_A + (size_t)((t * 16 + s) * 32 + lane) * 16) = w;
        }
        sqA += __shfl_xor_sync(0xffffffffu, sqA, 1);
        sqA += __shfl_xor_sync(0xffffffffu, sqA, 2);
        sqB += __shfl_xor_sync(0xffffffffu, sqB, 1);
        sqB += __shfl_xor_sync(0xffffffffu, sqB, 2);
        if (tig == 0) {
            s_fsq[t * 16 + g]     = sqA;
            s_fsq[t * 16 + g + 8] = sqB;
        }
    }

    // ---- All 512 prototype norms, exact fp32 (proto is L2-hot: 512 KB) ----
    {
        const float4* r = (const float4*)(proto + (size_t)tid * DIMK);
        float s0 = 0.f, s1 = 0.f, s2 = 0.f, s3 = 0.f;
#pragma unroll
        for (int j = 0; j < 64; j += 4) {
            float4 v0 = r[j], v1 = r[j + 1], v2 = r[j + 2], v3 = r[j + 3];
            s0 += v0.x * v0.x + v0.y * v0.y + v0.z * v0.z + v0.w * v0.w;
            s1 += v1.x * v1.x + v1.y * v1.y + v1.z * v1.z + v1.w * v1.w;
            s2 += v2.x * v2.x + v2.y * v2.y + v2.z * v2.z + v2.w * v2.w;
            s3 += v3.x * v3.x + v3.y * v3.y + v3.z * v3.z + v3.w * v3.w;
        }
        s_psq[tid] = (s0 + s1) + (s2 + s3);
    }

    // ---- B staging: chunk c (32 protos = 4 ntiles x 16 ksteps) into buf ----
    // warp w: ntile u = w>>2, kstep quarter = w&3.
    const int su = wid >> 2, sq = wid & 3;
    auto stage_B = [&](int c, char* buf) {
        const float* r = proto + (size_t)(c * BLK_N + su * 8 + g) * DIMK;
#pragma unroll
        for (int j = 0; j < 4; j++) {
            const int s  = sq * 4 + j;
            const int kA = s * 16 + 2 * tig;
            float2 f0 = *(const float2*)(r + kA);
            float2 f1 = *(const float2*)(r + kA + 8);
            uint2 w;
            w.x = pk(f0); w.y = pk(f1);
            *(uint2*)(buf + (size_t)((su * 16 + s) * 32 + lane) * 8) = w;
        }
    };

    stage_B(0, smem + SM_B0);
    __syncthreads();   // A frags + norms + B(chunk 0) visible

    // Per-warp constants for the epilogue
    const char* baseA = smem + SM_A + (size_t)lane * 16;
    float fsr[2][2];
    float* row1[2][2];
    int   mcol[2][2];
#pragma unroll
    for (int tp = 0; tp < 2; tp++) {
#pragma unroll
        for (int h = 0; h < 2; h++) {
            const int ml = mi * 32 + tp * 16 + h * 8 + g;
            fsr[tp][h]  = s_fsq[ml];
            row1[tp][h] = out1 + (size_t)(m0 + ml) * N_PROTO;
            mcol[tp][h] = m0 + ml;
        }
    }
    const int plbase = nj * 16 + 2 * tig;

    float accA[2][2][4], accB[2][2][4];

    // run one chunk: compute accC from bufC; store pend (chunk at p0p) if has_pend
    auto run_chunk = [&](float (&accC)[2][2][4], float (&pend)[2][2][4],
                         const char* bufC, bool has_pend, int p0p) {
#pragma unroll
        for (int tp = 0; tp < 2; tp++)
#pragma unroll
            for (int up = 0; up < 2; up++)
#pragma unroll
                for (int e = 0; e < 4; e++) accC[tp][up][e] = 0.f;

        if (has_pend) {
            // transform pending accumulators into distances, in place
#pragma unroll
            for (int q = 0; q < 4; q++) {
                const int tp = q >> 1, up = q & 1;
                const int pl = plbase + up * 8;
                const float2 ps = *(const float2*)(s_psq + p0p + pl);
                float* d = pend[tp][up];
                d[0] = fsr[tp][0] + ps.x - 2.0f * d[0];
                d[1] = fsr[tp][0] + ps.y - 2.0f * d[1];
                d[2] = fsr[tp][1] + ps.x - 2.0f * d[2];
                d[3] = fsr[tp][1] + ps.y - 2.0f * d[3];
            }
        }

#pragma unroll
        for (int s = 0; s < 16; s++) {
            uint4 a[2];
#pragma unroll
            for (int tp = 0; tp < 2; tp++)
                a[tp] = *(const uint4*)(baseA + (size_t)((mi * 2 + tp) * 16 + s) * 512);
            uint2 b[2];
#pragma unroll
            for (int up = 0; up < 2; up++)
                b[up] = *(const uint2*)(bufC + (size_t)(((nj * 2 + up) * 16 + s) * 32 + lane) * 8);
#pragma unroll
            for (int tp = 0; tp < 2; tp++)
#pragma unroll
                for (int up = 0; up < 2; up++)
                    mma_f16(accC[tp][up], (const uint32_t*)&a[tp], (const uint32_t*)&b[up]);

            // interleave 2 pending stores per k-step (24 stores over s=0..11)
            if (has_pend && s < 12) {
                const int q  = s >> 2;            // wrong pace? no: see mapping below
                const int j  = s & 3;
                // mapping: 12 ksteps = 4 pairs x 3 store-steps
                const int qq = s / 3, jj = s % 3;
                (void)q; (void)j;
                const int tp = qq >> 1, up = qq & 1;
                const int pl = plbase + up * 8;
                const float* d = pend[tp][up];
                if (jj == 0) {
                    // out1 [N,P]: full 32B sector per 4-lane quad
                    *(float2*)(row1[tp][0] + p0p + pl) = make_float2(d[0], d[1]);
                    *(float2*)(row1[tp][1] + p0p + pl) = make_float2(d[2], d[3]);
                } else if (jj == 1) {
                    // out2 [P,N]: 8 g-lanes = full 32B sector per column
                    out2[(size_t)(p0p + pl)     * N_FEAT + mcol[tp][0]] = d[0];
                    out2[(size_t)(p0p + pl + 1) * N_FEAT + mcol[tp][0]] = d[1];
                } else {
                    out2[(size_t)(p0p + pl)     * N_FEAT + mcol[tp][1]] = d[2];
                    out2[(size_t)(p0p + pl + 1) * N_FEAT + mcol[tp][1]] = d[3];
                }
            }
        }
    };

    for (int c2 = 0; c2 < 8; c2++) {
        const int cA = 2 * c2, cB = 2 * c2 + 1;
        // phase A: compute chunk cA (buf0); store chunk cA-1 (accB)
        stage_B(cB, smem + SM_B1);
        run_chunk(accA, accB, smem + SM_B0, c2 > 0, (cA - 1) * BLK_N);
        __syncthreads();   // buf1 ready; buf0 consumed
        // phase B: compute chunk cB (buf1); store chunk cA (accA)
        if (cB + 1 < N_CHUNKS) stage_B(cB + 1, smem + SM_B0);
        run_chunk(accB, accA, smem + SM_B1, true, cA * BLK_N);
        __syncthreads();   // buf0 ready; buf1 consumed
    }

    // ---- tail: store chunk 15 from accB ----
    {
        const int p0p = (N_CHUNKS - 1) * BLK_N;
#pragma unroll
        for (int q = 0; q < 4; q++) {
            const int tp = q >> 1, up = q & 1;
            const int pl = plbase + up * 8;
            const float2 ps = *(const float2*)(s_psq + p0p + pl);
            float* d = accB[tp][up];
            d[0] = fsr[tp][0] + ps.x - 2.0f * d[0];
            d[1] = fsr[tp][0] + ps.y - 2.0f * d[1];
            d[2] = fsr[tp][1] + ps.x - 2.0f * d[2];
            d[3] = fsr[tp][1] + ps.y - 2.0f * d[3];
            *(float2*)(row1[tp][0] + p0p + pl) = make_float2(d[0], d[1]);
            *(float2*)(row1[tp][1] + p0p + pl) = make_float2(d[2], d[3]);
            out2[(size_t)(p0p + pl)     * N_FEAT + mcol[tp][0]] = d[0];
            out2[(size_t)(p0p + pl + 1) * N_FEAT + mcol[tp][0]] = d[1];
            out2[(size_t)(p0p + pl)     * N_FEAT + mcol[tp][1]] = d[2];
            out2[(size_t)(p0p + pl + 1) * N_FEAT + mcol[tp][1]] = d[3];
        }
    }
}

// ---------------------------------------------------------------------------
// Launch
// ---------------------------------------------------------------------------
extern "C" void kernel_launch(void* const* d_in, const int* in_sizes, int n_in,
                              void* d_out, int out_size)
{
    (void)in_sizes; (void)n_in; (void)out_size;
    const float* feat  = (const float*)d_in[0];
    const float* proto = (const float*)d_in[1];
    float* out1 = (float*)d_out;
    float* out2 = out1 + (size_t)N_FEAT * N_PROTO;

    cudaFuncSetAttribute(proto_dist_kernel,
                         cudaFuncAttributeMaxDynamicSharedMemorySize, SMEM_TOTAL);

    proto_dist_kernel<<<N_FEAT / BLK_M, 512, SMEM_TOTAL>>>(feat, proto, out1, out2);
}